// round 5
// baseline (speedup 1.0000x reference)
#include <cuda_runtime.h>

#define BB 16
#define HH 2048
#define WW 2048
#define SS 5000
#define TOTAL (BB * SS)          // 80000 stations
#define THREADS 64
#define NBLK (TOTAL / THREADS)   // 1250 blocks, exact
#define NWARPS (TOTAL / 32)      // 2500 warps

__device__ float        g_sum;     // zero at module load; re-armed by last warp
__device__ unsigned int g_count;   // zero at module load; re-armed by last warp

__device__ __forceinline__ unsigned atomic_inc_acqrel(unsigned int* p) {
    unsigned old;
    asm volatile("atom.acq_rel.gpu.global.add.u32 %0, [%1], %2;"
                 : "=r"(old) : "l"(p), "r"(1u) : "memory");
    return old;
}

__device__ __forceinline__ void red_add_f32(float* p, float v) {
    asm volatile("red.global.add.f32 [%0], %1;" :: "l"(p), "f"(v) : "memory");
}

__global__ void __launch_bounds__(THREADS)
station_loss_kernel(const float* __restrict__ pred,
                    const int*   __restrict__ pos,
                    const float* __restrict__ runoff,
                    float*       __restrict__ out)
{
    int idx = blockIdx.x * THREADS + threadIdx.x;   // always < TOTAL (exact grid)

    int b  = idx / SS;
    int2 p = __ldg(reinterpret_cast<const int2*>(pos) + idx);
    int px = p.x;   // width index
    int py = p.y;   // height index

    const float* base = pred + (size_t)b * (size_t)(HH * WW);
    float avg;

    if (px >= 1 && px <= WW - 2 && py >= 1 && py <= HH - 2) {
        // Fast path (99.8% of stations): all 9 taps valid, cnt = 9.
        // Cover [px-1, px+1] with two aligned float2 loads per row.
        int a   = (px - 1) >> 1;
        int off = (px - 1) & 1;
        const float2* r0 = reinterpret_cast<const float2*>(base + (size_t)(py - 1) * WW);
        const float2* r1 = reinterpret_cast<const float2*>(base + (size_t)(py    ) * WW);
        const float2* r2 = reinterpret_cast<const float2*>(base + (size_t)(py + 1) * WW);

        float2 a0 = __ldg(r0 + a), b0 = __ldg(r0 + a + 1);
        float2 a1 = __ldg(r1 + a), b1 = __ldg(r1 + a + 1);
        float2 a2 = __ldg(r2 + a), b2 = __ldg(r2 + a + 1);

        float s0 = off ? (a0.y + b0.x + b0.y) : (a0.x + a0.y + b0.x);
        float s1 = off ? (a1.y + b1.x + b1.y) : (a1.x + a1.y + b1.x);
        float s2 = off ? (a2.y + b2.x + b2.y) : (a2.x + a2.y + b2.x);
        avg = (s0 + s1 + s2) * (1.0f / 9.0f);
    } else {
        // Edge path (rare): masked 9-tap with clamped coords.
        float sum = 0.0f, cnt = 0.0f;
        #pragma unroll
        for (int dy = -1; dy <= 1; ++dy) {
            int y   = py + dy;
            bool vy = (y >= 0) & (y < HH);
            int yc  = min(max(y, 0), HH - 1);
            const float* row = base + (size_t)yc * WW;
            #pragma unroll
            for (int dx = -1; dx <= 1; ++dx) {
                int x  = px + dx;
                bool v = vy & (x >= 0) & (x < WW);
                int xc = min(max(x, 0), WW - 1);
                float val = __ldg(row + xc);
                sum += v ? val  : 0.0f;
                cnt += v ? 1.0f : 0.0f;
            }
        }
        avg = sum / cnt;
    }

    float d    = avg - __ldg(runoff + idx);
    float err2 = d * d;

    // Warp reduction only — no smem, no __syncthreads.
    #pragma unroll
    for (int off = 16; off > 0; off >>= 1)
        err2 += __shfl_down_sync(0xFFFFFFFFu, err2, off);

    if ((threadIdx.x & 31) == 0) {
        red_add_f32(&g_sum, err2);                    // pipelined L2 RED, no return
        unsigned done = atomic_inc_acqrel(&g_count);  // release orders the RED
        if (done == NWARPS - 1) {
            float s;
            asm volatile("ld.acquire.gpu.global.f32 %0, [%1];"
                         : "=f"(s) : "l"(&g_sum));
            out[0]  = s * (1.0f / (float)TOTAL);
            g_sum   = 0.0f;   // re-arm for next graph replay
            g_count = 0u;
        }
    }
}

extern "C" void kernel_launch(void* const* d_in, const int* in_sizes, int n_in,
                              void* d_out, int out_size)
{
    const float* pred   = (const float*)d_in[0];  // (B,1,H,W) f32
    const int*   pos    = (const int*)  d_in[1];  // (B,S,2)  i32
    const float* runoff = (const float*)d_in[2];  // (B,S)    f32
    float* out = (float*)d_out;

    station_loss_kernel<<<NBLK, THREADS>>>(pred, pos, runoff, out);
}

// round 7
// speedup vs baseline: 1.2399x; 1.2399x over previous
#include <cuda_runtime.h>

#define BB 16
#define HH 2048
#define WW 2048
#define SS 5000
#define TOTAL (BB * SS)            // 80000 stations
#define THREADS 320                // 10 warps; 250 * 320 == 80000 exactly
#define NBLK (TOTAL / THREADS)     // 250 blocks
#define NWARP (THREADS / 32)       // 10

__device__ float        g_partials[NBLK];
__device__ unsigned int g_count;   // zero at module load; re-armed by last block

__device__ __forceinline__ unsigned atomic_inc_acqrel(unsigned int* p) {
    unsigned old;
    asm volatile("atom.acq_rel.gpu.global.add.u32 %0, [%1], %2;"
                 : "=r"(old) : "l"(p), "r"(1u) : "memory");
    return old;
}

__device__ __forceinline__ float row_sum3(const float* rowbase, int a4, int off) {
    const float4* r = reinterpret_cast<const float4*>(rowbase);
    float4 v0 = __ldg(r + a4);
    float4 v1 = make_float4(0.f, 0.f, 0.f, 0.f);
    if (off >= 2) v1 = __ldg(r + a4 + 1);   // predicated: only when span crosses
    float s;
    if      (off == 0) s = v0.x + v0.y + v0.z;
    else if (off == 1) s = v0.y + v0.z + v0.w;
    else if (off == 2) s = v0.z + v0.w + v1.x;
    else               s = v0.w + v1.x + v1.y;
    return s;
}

__device__ __forceinline__ float warp_reduce(float v) {
    #pragma unroll
    for (int off = 16; off > 0; off >>= 1)
        v += __shfl_down_sync(0xFFFFFFFFu, v, off);
    return v;
}

__global__ void __launch_bounds__(THREADS)
station_loss_kernel(const float* __restrict__ pred,
                    const int*   __restrict__ pos,
                    const float* __restrict__ runoff,
                    float*       __restrict__ out)
{
    int idx = blockIdx.x * THREADS + threadIdx.x;   // exact grid, no bounds check

    int b  = idx / SS;
    int2 p = __ldg(reinterpret_cast<const int2*>(pos) + idx);
    int px = p.x;   // width index
    int py = p.y;   // height index

    const float* base = pred + (size_t)b * (size_t)(HH * WW);
    float avg;

    if (px >= 1 && px <= WW - 2 && py >= 1 && py <= HH - 2) {
        // Fast path (~99.8%): all 9 taps valid, cnt = 9.
        int a4  = (px - 1) >> 2;
        int off = (px - 1) & 3;
        float s0 = row_sum3(base + (size_t)(py - 1) * WW, a4, off);
        float s1 = row_sum3(base + (size_t)(py    ) * WW, a4, off);
        float s2 = row_sum3(base + (size_t)(py + 1) * WW, a4, off);
        avg = (s0 + s1 + s2) * (1.0f / 9.0f);
    } else {
        // Edge path (rare): masked 9-tap with clamped coords.
        float sum = 0.0f, cnt = 0.0f;
        #pragma unroll
        for (int dy = -1; dy <= 1; ++dy) {
            int y   = py + dy;
            bool vy = (y >= 0) & (y < HH);
            int yc  = min(max(y, 0), HH - 1);
            const float* row = base + (size_t)yc * WW;
            #pragma unroll
            for (int dx = -1; dx <= 1; ++dx) {
                int x  = px + dx;
                bool v = vy & (x >= 0) & (x < WW);
                int xc = min(max(x, 0), WW - 1);
                float val = __ldg(row + xc);
                sum += v ? val  : 0.0f;
                cnt += v ? 1.0f : 0.0f;
            }
        }
        avg = sum / cnt;
    }

    float d    = avg - __ldg(runoff + idx);
    float err2 = d * d;

    // Deterministic block reduction: warp shuffle then fixed-order sum of 10.
    __shared__ float warp_sums[NWARP];
    err2 = warp_reduce(err2);

    int lane = threadIdx.x & 31;
    int wid  = threadIdx.x >> 5;
    if (lane == 0) warp_sums[wid] = err2;
    __syncthreads();

    __shared__ bool is_last;
    if (threadIdx.x == 0) {
        float v = 0.0f;
        #pragma unroll
        for (int i = 0; i < NWARP; ++i)
            v += warp_sums[i];
        g_partials[blockIdx.x] = v;
        unsigned done = atomic_inc_acqrel(&g_count);   // release orders the store
        is_last = (done == NBLK - 1);
    }
    __syncthreads();

    // Last block: deterministic final reduction over 250 partials.
    // Strided accumulate -> warp shuffle -> fixed-order sum of 10 warp sums.
    if (is_last) {
        float v = 0.0f;
        for (int i = threadIdx.x; i < NBLK; i += THREADS)
            v += __ldcg(&g_partials[i]);
        v = warp_reduce(v);

        __shared__ float fin[NWARP];
        if (lane == 0) fin[wid] = v;
        __syncthreads();
        if (threadIdx.x == 0) {
            float s = 0.0f;
            #pragma unroll
            for (int i = 0; i < NWARP; ++i)
                s += fin[i];
            out[0]  = s / (float)TOTAL;
            g_count = 0u;   // re-arm for next graph replay
        }
    }
}

extern "C" void kernel_launch(void* const* d_in, const int* in_sizes, int n_in,
                              void* d_out, int out_size)
{
    const float* pred   = (const float*)d_in[0];  // (B,1,H,W) f32
    const int*   pos    = (const int*)  d_in[1];  // (B,S,2)  i32
    const float* runoff = (const float*)d_in[2];  // (B,S)    f32
    float* out = (float*)d_out;

    station_loss_kernel<<<NBLK, THREADS>>>(pred, pos, runoff, out);
}